// round 7
// baseline (speedup 1.0000x reference)
#include <cuda_runtime.h>

#define MUL   16
#define DD    4
#define S0    8
#define S1    8
#define SOUT  8
#define NP3   8
#define NP4   4
#define EPB   8
#define THREADS 128
#define GRID_BLOCKS 912   // 152 SMs * 6 resident blocks

#define X1PAD 36          // sX1 per-edge stride (bank offset 4)
#define WPAD  196         // sW per-edge stride (bank offset 4)

// packed metadata built once by prep_kernel
__device__ int d_meta[6];    // 12 x 16-bit: s0 | slot<<4 | so<<8 | flush<<12
__device__ int d_zmask;      // bit so: no path writes this sout
__device__ int d_p3pack;     // s1 (3b) per rank-3 path
__device__ int d_p4pack;     // s1a,s1b (3b each) per rank-4 path

__global__ void prep_kernel(const int* __restrict__ p3, const int* __restrict__ p4) {
    if (threadIdx.x == 0 && blockIdx.x == 0) {
        unsigned int ent[NP3 + NP4];
        int n = 0, zm = 0;
        for (int so = 0; so < SOUT; ++so) {
            int start = n;
            for (int p = 0; p < NP3; ++p)
                if (p3[p * 3 + 2] == so)
                    ent[n++] = (unsigned)(p3[p * 3 + 0]) | ((unsigned)p << 4) | ((unsigned)so << 8);
            for (int p = 0; p < NP4; ++p)
                if (p4[p * 4 + 3] == so)
                    ent[n++] = (unsigned)(p4[p * 4 + 0]) | ((unsigned)(NP3 + p) << 4) | ((unsigned)so << 8);
            if (n == start) zm |= (1 << so);
            else            ent[n - 1] |= (1u << 12);
        }
        for (int i = 0; i < 6; ++i)
            d_meta[i] = (int)(ent[2 * i] | (ent[2 * i + 1] << 16));
        d_zmask = zm;
        int pp3 = 0, pp4 = 0;
        for (int p = 0; p < NP3; ++p) pp3 |= (p3[p * 3 + 1] & 7) << (3 * p);
        for (int p = 0; p < NP4; ++p) {
            pp4 |= (p4[p * 4 + 1] & 7) << (6 * p);
            pp4 |= (p4[p * 4 + 2] & 7) << (6 * p + 3);
        }
        d_p3pack = pp3;
        d_p4pack = pp4;
    }
}

// uniform-index register select (s is uniform across the block)
__device__ __forceinline__ float4 sel8(const float4 a[8], int s) {
    switch (s) {
        case 0: return a[0]; case 1: return a[1];
        case 2: return a[2]; case 3: return a[3];
        case 4: return a[4]; case 5: return a[5];
        case 6: return a[6]; default: return a[7];
    }
}

__global__ __launch_bounds__(THREADS, 6) void tp_kernel(
    const float* __restrict__ x0, const int* __restrict__ i0,
    const float* __restrict__ x1,
    const float* __restrict__ C3, const float* __restrict__ C4,
    float* __restrict__ out, int E)
{
    __shared__ float sC4T[16 * 64];      // [jk][u*4+m]  conflict-free
    __shared__ float sC3T[4 * 128];      // [j][job*4+k] conflict-free
    __shared__ float sX1[EPB * X1PAD];   // padded: half-warps on different banks
    __shared__ float sW[EPB * WPAD];     // padded: half-warps on different banks

    const int tid = threadIdx.x;
    const int el  = tid >> 4;
    const int u   = tid & 15;

    // one-time staging (transposed, conflict-free layouts)
    for (int idx = tid; idx < 1024; idx += THREADS) {
        int uu = idx >> 6, r = idx & 63, jk = r >> 2, m = r & 3;
        sC4T[jk * 64 + uu * 4 + m] = C4[idx];
    }
    for (int idx = tid; idx < 512; idx += THREADS) {
        int job = idx >> 4, r = idx & 15, j = r >> 2, k = r & 3;
        sC3T[j * 128 + job * 4 + k] = C3[idx];
    }

    // loop-invariant metadata -> registers
    int meta[6];
    #pragma unroll
    for (int i = 0; i < 6; ++i) meta[i] = d_meta[i];
    const int zmask = d_zmask;
    const int pp3 = d_p3pack;
    const int pp4 = d_p4pack;

    // fixed per-thread W-phase path slots
    const int p4p = u >> 2;
    const int s1a = (pp4 >> (6 * p4p)) & 7;
    const int s1b = (pp4 >> (6 * p4p + 3)) & 7;
    const int s1c0 = (pp3 >> (3 * (u >> 2))) & 7;          // job = u
    const int s1c1 = (pp3 >> (3 * ((u + 16) >> 2))) & 7;   // job = u + 16

    const float* myX1 = &sX1[el * X1PAD];
    float* myW = &sW[el * WPAD];

    __syncthreads();

    const int ngroups = (E + EPB - 1) / EPB;

    for (int g = blockIdx.x; g < ngroups; g += GRID_BLOCKS) {
        const int e  = g * EPB + el;
        const bool valid = (e < E);
        const int ec = valid ? e : (E - 1);

        // x0 row -> registers (8 independent LDG.128)
        float4 a[8];
        const long long row = (long long)__ldg(&i0[ec]) * (S0 * MUL * DD);
        #pragma unroll
        for (int c = 0; c < 8; ++c)
            a[c] = __ldg((const float4*)&x0[row + c * 64 + u * 4]);
        // x1 -> padded shared
        if (u < 8) {
            float4 v = __ldg((const float4*)&x1[(long long)ec * (S1 * DD) + u * 4]);
            *(float4*)&sX1[el * X1PAD + u * 4] = v;
        }
        __syncwarp();

        // ---- W phase: vector (LDS.128) b-value reads, products in registers ----
        {   // rank-4 job (p = u>>2, i = u&3)
            const float4 bq = *(const float4*)&myX1[s1a * 4];
            const float4 cq = *(const float4*)&myX1[s1b * 4];
            const float bv[4] = {bq.x, bq.y, bq.z, bq.w};
            const float cv[4] = {cq.x, cq.y, cq.z, cq.w};
            float4 w = make_float4(0.f, 0.f, 0.f, 0.f);
            #pragma unroll
            for (int j = 0; j < 4; ++j) {
                #pragma unroll
                for (int k = 0; k < 4; ++k) {
                    const float bc = bv[j] * cv[k];
                    const float4 cf = *(const float4*)&sC4T[(j * 4 + k) * 64 + u * 4];
                    w.x += bc * cf.x; w.y += bc * cf.y;
                    w.z += bc * cf.z; w.w += bc * cf.w;
                }
            }
            *(float4*)&myW[128 + u * 4] = w;   // slot 8+p, row i
        }
        {   // rank-3 job h=0 (job = u)
            const float4 bq = *(const float4*)&myX1[s1c0 * 4];
            const float bv[4] = {bq.x, bq.y, bq.z, bq.w};
            float4 w = make_float4(0.f, 0.f, 0.f, 0.f);
            #pragma unroll
            for (int j = 0; j < 4; ++j) {
                const float4 cf = *(const float4*)&sC3T[j * 128 + u * 4];
                w.x += bv[j] * cf.x; w.y += bv[j] * cf.y;
                w.z += bv[j] * cf.z; w.w += bv[j] * cf.w;
            }
            *(float4*)&myW[u * 4] = w;
        }
        {   // rank-3 job h=1 (job = u+16)
            const float4 bq = *(const float4*)&myX1[s1c1 * 4];
            const float bv[4] = {bq.x, bq.y, bq.z, bq.w};
            float4 w = make_float4(0.f, 0.f, 0.f, 0.f);
            #pragma unroll
            for (int j = 0; j < 4; ++j) {
                const float4 cf = *(const float4*)&sC3T[j * 128 + (u + 16) * 4];
                w.x += bv[j] * cf.x; w.y += bv[j] * cf.y;
                w.z += bv[j] * cf.z; w.w += bv[j] * cf.w;
            }
            *(float4*)&myW[(u + 16) * 4] = w;
        }
        __syncwarp();

        // ---- contraction: fully unrolled 12 sorted entries, flush at group end ----
        const long long obase = (long long)e * (SOUT * MUL * DD);
        float4 acc = make_float4(0.f, 0.f, 0.f, 0.f);
        #pragma unroll
        for (int t = 0; t < 12; ++t) {
            const int w16  = (meta[t >> 1] >> ((t & 1) * 16)) & 0xffff;
            const int s0v  = w16 & 7;
            const int slot = (w16 >> 4) & 15;
            const float4 av = sel8(a, s0v);
            const float4* Wp = (const float4*)&myW[slot * 16];
            const float4 w0 = Wp[0], w1 = Wp[1], w2 = Wp[2], w3 = Wp[3];
            acc.x += av.x * w0.x + av.y * w1.x + av.z * w2.x + av.w * w3.x;
            acc.y += av.x * w0.y + av.y * w1.y + av.z * w2.y + av.w * w3.y;
            acc.z += av.x * w0.z + av.y * w1.z + av.z * w2.z + av.w * w3.z;
            acc.w += av.x * w0.w + av.y * w1.w + av.z * w2.w + av.w * w3.w;
            if (w16 & (1 << 12)) {           // uniform predicate
                const int so = (w16 >> 8) & 7;
                if (valid)
                    __stwt((float4*)&out[obase + so * 64 + u * 4], acc);
                acc = make_float4(0.f, 0.f, 0.f, 0.f);
            }
        }
        if (valid && zmask) {
            const float4 z = make_float4(0.f, 0.f, 0.f, 0.f);
            #pragma unroll
            for (int so = 0; so < SOUT; ++so)
                if ((zmask >> so) & 1)
                    __stwt((float4*)&out[obase + so * 64 + u * 4], z);
        }
        __syncwarp();   // protect sX1/sW reuse next iteration
    }
}

extern "C" void kernel_launch(void* const* d_in, const int* in_sizes, int n_in,
                              void* d_out, int out_size) {
    const float* x0 = (const float*)d_in[0];
    const int*   i0 = (const int*)d_in[1];
    const float* x1 = (const float*)d_in[2];
    const float* C3 = (const float*)d_in[3];
    const float* C4 = (const float*)d_in[4];
    const int*   p3 = (const int*)d_in[5];
    const int*   p4 = (const int*)d_in[6];
    float* out = (float*)d_out;
    const int E = in_sizes[1];

    prep_kernel<<<1, 32>>>(p3, p4);
    const int ngroups = (E + EPB - 1) / EPB;
    const int blocks = ngroups < GRID_BLOCKS ? ngroups : GRID_BLOCKS;
    tp_kernel<<<blocks, THREADS>>>(x0, i0, x1, C3, C4, out, E);
}

// round 8
// speedup vs baseline: 1.0388x; 1.0388x over previous
#include <cuda_runtime.h>

#define MUL   16
#define DD    4
#define S0    8
#define S1    8
#define SOUT  8
#define NP3   8
#define NP4   4
#define EPB   8
#define THREADS 128
#define GRID_BLOCKS 912   // 152 SMs * 6 resident blocks

#define X1PAD 36
#define WPAD  196

typedef unsigned long long u64;

__device__ int d_meta[6];
__device__ int d_zmask;
__device__ int d_p3pack;
__device__ int d_p4pack;

__global__ void prep_kernel(const int* __restrict__ p3, const int* __restrict__ p4) {
    if (threadIdx.x == 0 && blockIdx.x == 0) {
        unsigned int ent[NP3 + NP4];
        int n = 0, zm = 0;
        for (int so = 0; so < SOUT; ++so) {
            int start = n;
            for (int p = 0; p < NP3; ++p)
                if (p3[p * 3 + 2] == so)
                    ent[n++] = (unsigned)(p3[p * 3 + 0]) | ((unsigned)p << 4) | ((unsigned)so << 8);
            for (int p = 0; p < NP4; ++p)
                if (p4[p * 4 + 3] == so)
                    ent[n++] = (unsigned)(p4[p * 4 + 0]) | ((unsigned)(NP3 + p) << 4) | ((unsigned)so << 8);
            if (n == start) zm |= (1 << so);
            else            ent[n - 1] |= (1u << 12);
        }
        for (int i = 0; i < 6; ++i)
            d_meta[i] = (int)(ent[2 * i] | (ent[2 * i + 1] << 16));
        d_zmask = zm;
        int pp3 = 0, pp4 = 0;
        for (int p = 0; p < NP3; ++p) pp3 |= (p3[p * 3 + 1] & 7) << (3 * p);
        for (int p = 0; p < NP4; ++p) {
            pp4 |= (p4[p * 4 + 1] & 7) << (6 * p);
            pp4 |= (p4[p * 4 + 2] & 7) << (6 * p + 3);
        }
        d_p3pack = pp3;
        d_p4pack = pp4;
    }
}

// packed f32x2 helpers (FFMA2 is PTX-only)
__device__ __forceinline__ u64 dup2(float x) {
    u64 r;
    asm("mov.b64 %0, {%1, %1};" : "=l"(r) : "r"(__float_as_uint(x)));
    return r;
}
__device__ __forceinline__ u64 fma2(u64 a, u64 b, u64 c) {
    u64 d;
    asm("fma.rn.f32x2 %0, %1, %2, %3;" : "=l"(d) : "l"(a), "l"(b), "l"(c));
    return d;
}
__device__ __forceinline__ float2 unpack2(u64 v) {
    float2 f;
    unsigned lo, hi;
    asm("mov.b64 {%0, %1}, %2;" : "=r"(lo), "=r"(hi) : "l"(v));
    f.x = __uint_as_float(lo); f.y = __uint_as_float(hi);
    return f;
}

__device__ __forceinline__ float4 sel8(const float4 a[8], int s) {
    switch (s) {
        case 0: return a[0]; case 1: return a[1];
        case 2: return a[2]; case 3: return a[3];
        case 4: return a[4]; case 5: return a[5];
        case 6: return a[6]; default: return a[7];
    }
}

__global__ __launch_bounds__(THREADS, 6) void tp_kernel(
    const float* __restrict__ x0, const int* __restrict__ i0,
    const float* __restrict__ x1,
    const float* __restrict__ C3, const float* __restrict__ C4,
    float* __restrict__ out, int E)
{
    __shared__ float sC4T[16 * 64];
    __shared__ float sC3T[4 * 128];
    __shared__ float sX1[EPB * X1PAD];
    __shared__ float sW[EPB * WPAD];

    const int tid = threadIdx.x;
    const int el  = tid >> 4;
    const int u   = tid & 15;

    for (int idx = tid; idx < 1024; idx += THREADS) {
        int uu = idx >> 6, r = idx & 63, jk = r >> 2, m = r & 3;
        sC4T[jk * 64 + uu * 4 + m] = C4[idx];
    }
    for (int idx = tid; idx < 512; idx += THREADS) {
        int job = idx >> 4, r = idx & 15, j = r >> 2, k = r & 3;
        sC3T[j * 128 + job * 4 + k] = C3[idx];
    }

    int meta[6];
    #pragma unroll
    for (int i = 0; i < 6; ++i) meta[i] = d_meta[i];
    const int zmask = d_zmask;
    const int pp3 = d_p3pack;
    const int pp4 = d_p4pack;

    const int p4p = u >> 2;
    const int s1a = (pp4 >> (6 * p4p)) & 7;
    const int s1b = (pp4 >> (6 * p4p + 3)) & 7;
    const int s1c0 = (pp3 >> (3 * (u >> 2))) & 7;
    const int s1c1 = (pp3 >> (3 * ((u + 16) >> 2))) & 7;

    const float* myX1 = &sX1[el * X1PAD];
    float* myW = &sW[el * WPAD];

    __syncthreads();

    const int ngroups = (E + EPB - 1) / EPB;

    for (int g = blockIdx.x; g < ngroups; g += GRID_BLOCKS) {
        const int e  = g * EPB + el;
        const bool valid = (e < E);
        const int ec = valid ? e : (E - 1);

        float4 a[8];
        const long long row = (long long)__ldg(&i0[ec]) * (S0 * MUL * DD);
        #pragma unroll
        for (int c = 0; c < 8; ++c)
            a[c] = __ldg((const float4*)&x0[row + c * 64 + u * 4]);
        if (u < 8) {
            float4 v = __ldg((const float4*)&x1[(long long)ec * (S1 * DD) + u * 4]);
            *(float4*)&sX1[el * X1PAD + u * 4] = v;
        }
        __syncwarp();

        // ---- W phase (packed f32x2 accumulation) ----
        {   // rank-4 job (p = u>>2, i = u&3)
            const float4 bq = *(const float4*)&myX1[s1a * 4];
            const float4 cq = *(const float4*)&myX1[s1b * 4];
            const float bv[4] = {bq.x, bq.y, bq.z, bq.w};
            const float cv[4] = {cq.x, cq.y, cq.z, cq.w};
            u64 w01 = 0ull, w23 = 0ull;
            #pragma unroll
            for (int j = 0; j < 4; ++j) {
                #pragma unroll
                for (int k = 0; k < 4; ++k) {
                    const u64 bc = dup2(bv[j] * cv[k]);
                    const ulonglong2 cf = *(const ulonglong2*)&sC4T[(j * 4 + k) * 64 + u * 4];
                    w01 = fma2(bc, cf.x, w01);
                    w23 = fma2(bc, cf.y, w23);
                }
            }
            *(ulonglong2*)&myW[128 + u * 4] = make_ulonglong2(w01, w23);
        }
        {   // rank-3 job h=0 (job = u)
            const float4 bq = *(const float4*)&myX1[s1c0 * 4];
            const float bv[4] = {bq.x, bq.y, bq.z, bq.w};
            u64 w01 = 0ull, w23 = 0ull;
            #pragma unroll
            for (int j = 0; j < 4; ++j) {
                const u64 bj = dup2(bv[j]);
                const ulonglong2 cf = *(const ulonglong2*)&sC3T[j * 128 + u * 4];
                w01 = fma2(bj, cf.x, w01);
                w23 = fma2(bj, cf.y, w23);
            }
            *(ulonglong2*)&myW[u * 4] = make_ulonglong2(w01, w23);
        }
        {   // rank-3 job h=1 (job = u+16)
            const float4 bq = *(const float4*)&myX1[s1c1 * 4];
            const float bv[4] = {bq.x, bq.y, bq.z, bq.w};
            u64 w01 = 0ull, w23 = 0ull;
            #pragma unroll
            for (int j = 0; j < 4; ++j) {
                const u64 bj = dup2(bv[j]);
                const ulonglong2 cf = *(const ulonglong2*)&sC3T[j * 128 + (u + 16) * 4];
                w01 = fma2(bj, cf.x, w01);
                w23 = fma2(bj, cf.y, w23);
            }
            *(ulonglong2*)&myW[(u + 16) * 4] = make_ulonglong2(w01, w23);
        }
        __syncwarp();

        // ---- contraction (packed f32x2): 12 sorted entries, flush at group end ----
        const long long obase = (long long)e * (SOUT * MUL * DD);
        u64 acc01 = 0ull, acc23 = 0ull;
        #pragma unroll
        for (int t = 0; t < 12; ++t) {
            const int w16  = (meta[t >> 1] >> ((t & 1) * 16)) & 0xffff;
            const int s0v  = w16 & 7;
            const int slot = (w16 >> 4) & 15;
            const float4 av = sel8(a, s0v);
            const ulonglong2 W0 = *(const ulonglong2*)&myW[slot * 16];      // w0.xy, w0.zw
            const ulonglong2 W1 = *(const ulonglong2*)&myW[slot * 16 + 4];  // w1.xy, w1.zw
            const ulonglong2 W2 = *(const ulonglong2*)&myW[slot * 16 + 8];
            const ulonglong2 W3 = *(const ulonglong2*)&myW[slot * 16 + 12];
            const u64 ax = dup2(av.x), ay = dup2(av.y), az = dup2(av.z), aw = dup2(av.w);
            acc01 = fma2(ax, W0.x, acc01); acc23 = fma2(ax, W0.y, acc23);
            acc01 = fma2(ay, W1.x, acc01); acc23 = fma2(ay, W1.y, acc23);
            acc01 = fma2(az, W2.x, acc01); acc23 = fma2(az, W2.y, acc23);
            acc01 = fma2(aw, W3.x, acc01); acc23 = fma2(aw, W3.y, acc23);
            if (w16 & (1 << 12)) {
                const int so = (w16 >> 8) & 7;
                if (valid) {
                    const float2 lo = unpack2(acc01);
                    const float2 hi = unpack2(acc23);
                    __stwt((float4*)&out[obase + so * 64 + u * 4],
                           make_float4(lo.x, lo.y, hi.x, hi.y));
                }
                acc01 = 0ull; acc23 = 0ull;
            }
        }
        if (valid && zmask) {
            const float4 z = make_float4(0.f, 0.f, 0.f, 0.f);
            #pragma unroll
            for (int so = 0; so < SOUT; ++so)
                if ((zmask >> so) & 1)
                    __stwt((float4*)&out[obase + so * 64 + u * 4], z);
        }
        __syncwarp();
    }
}

extern "C" void kernel_launch(void* const* d_in, const int* in_sizes, int n_in,
                              void* d_out, int out_size) {
    const float* x0 = (const float*)d_in[0];
    const int*   i0 = (const int*)d_in[1];
    const float* x1 = (const float*)d_in[2];
    const float* C3 = (const float*)d_in[3];
    const float* C4 = (const float*)d_in[4];
    const int*   p3 = (const int*)d_in[5];
    const int*   p4 = (const int*)d_in[6];
    float* out = (float*)d_out;
    const int E = in_sizes[1];

    prep_kernel<<<1, 32>>>(p3, p4);
    const int ngroups = (E + EPB - 1) / EPB;
    const int blocks = ngroups < GRID_BLOCKS ? ngroups : GRID_BLOCKS;
    tp_kernel<<<blocks, THREADS>>>(x0, i0, x1, C3, C4, out, E);
}

// round 10
// speedup vs baseline: 1.0788x; 1.0385x over previous
#include <cuda_runtime.h>

#define MUL   16
#define DD    4
#define S0    8
#define S1    8
#define SOUT  8
#define NP3   8
#define NP4   4
#define EPB   8
#define THREADS 128
#define GRID_BLOCKS 1216   // 152 SMs * 8 resident blocks

#define X1PAD 36
#define WPAD  196

typedef unsigned long long u64;

__device__ int d_meta[6];
__device__ int d_zmask;
__device__ int d_p3pack;
__device__ int d_p4pack;

__global__ void prep_kernel(const int* __restrict__ p3, const int* __restrict__ p4) {
    if (threadIdx.x == 0 && blockIdx.x == 0) {
        unsigned int ent[NP3 + NP4];
        int n = 0, zm = 0;
        for (int so = 0; so < SOUT; ++so) {
            int start = n;
            for (int p = 0; p < NP3; ++p)
                if (p3[p * 3 + 2] == so)
                    ent[n++] = (unsigned)(p3[p * 3 + 0]) | ((unsigned)p << 4) | ((unsigned)so << 8);
            for (int p = 0; p < NP4; ++p)
                if (p4[p * 4 + 3] == so)
                    ent[n++] = (unsigned)(p4[p * 4 + 0]) | ((unsigned)(NP3 + p) << 4) | ((unsigned)so << 8);
            if (n == start) zm |= (1 << so);
            else            ent[n - 1] |= (1u << 12);
        }
        for (int i = 0; i < 6; ++i)
            d_meta[i] = (int)(ent[2 * i] | (ent[2 * i + 1] << 16));
        d_zmask = zm;
        int pp3 = 0, pp4 = 0;
        for (int p = 0; p < NP3; ++p) pp3 |= (p3[p * 3 + 1] & 7) << (3 * p);
        for (int p = 0; p < NP4; ++p) {
            pp4 |= (p4[p * 4 + 1] & 7) << (6 * p);
            pp4 |= (p4[p * 4 + 2] & 7) << (6 * p + 3);
        }
        d_p3pack = pp3;
        d_p4pack = pp4;
    }
}

// packed f32x2 helpers (FFMA2 is PTX-only)
__device__ __forceinline__ u64 dup2(float x) {
    u64 r;
    asm("mov.b64 %0, {%1, %1};" : "=l"(r) : "r"(__float_as_uint(x)));
    return r;
}
__device__ __forceinline__ u64 fma2(u64 a, u64 b, u64 c) {
    u64 d;
    asm("fma.rn.f32x2 %0, %1, %2, %3;" : "=l"(d) : "l"(a), "l"(b), "l"(c));
    return d;
}
__device__ __forceinline__ float2 unpack2(u64 v) {
    float2 f;
    unsigned lo, hi;
    asm("mov.b64 {%0, %1}, %2;" : "=r"(lo), "=r"(hi) : "l"(v));
    f.x = __uint_as_float(lo); f.y = __uint_as_float(hi);
    return f;
}

__device__ __forceinline__ float4 sel8(const float4 a[8], int s) {
    switch (s) {
        case 0: return a[0]; case 1: return a[1];
        case 2: return a[2]; case 3: return a[3];
        case 4: return a[4]; case 5: return a[5];
        case 6: return a[6]; default: return a[7];
    }
}

template <bool FULL>
__global__ __launch_bounds__(THREADS, 8) void tp_kernel(
    const float* __restrict__ x0, const int* __restrict__ i0,
    const float* __restrict__ x1,
    const float* __restrict__ C3, const float* __restrict__ C4,
    float* __restrict__ out, int E)
{
    __shared__ float sC4T[16 * 64];
    __shared__ float sC3T[4 * 128];
    __shared__ float sX1[EPB * X1PAD];
    __shared__ float sW[EPB * WPAD];

    const int tid = threadIdx.x;
    const int el  = tid >> 4;
    const int u   = tid & 15;

    for (int idx = tid; idx < 1024; idx += THREADS) {
        int uu = idx >> 6, r = idx & 63, jk = r >> 2, m = r & 3;
        sC4T[jk * 64 + uu * 4 + m] = C4[idx];
    }
    for (int idx = tid; idx < 512; idx += THREADS) {
        int job = idx >> 4, r = idx & 15, j = r >> 2, k = r & 3;
        sC3T[j * 128 + job * 4 + k] = C3[idx];
    }

    int meta[6];
    #pragma unroll
    for (int i = 0; i < 6; ++i) meta[i] = d_meta[i];
    const int zmask = d_zmask;
    const int pp3 = d_p3pack;
    const int pp4 = d_p4pack;

    const int p4p = u >> 2;
    const int s1a = (pp4 >> (6 * p4p)) & 7;
    const int s1b = (pp4 >> (6 * p4p + 3)) & 7;
    const int s1c0 = (pp3 >> (3 * (u >> 2))) & 7;
    const int s1c1 = (pp3 >> (3 * ((u + 16) >> 2))) & 7;

    const float* myX1 = &sX1[el * X1PAD];
    float* myW = &sW[el * WPAD];

    __syncthreads();

    const int ngroups = (E + EPB - 1) / EPB;

    for (int g = blockIdx.x; g < ngroups; g += GRID_BLOCKS) {
        const int e  = g * EPB + el;
        const bool valid = FULL ? true : (e < E);
        const int ec = FULL ? e : (valid ? e : (E - 1));

        float4 a[8];
        const long long row = (long long)__ldg(&i0[ec]) * (S0 * MUL * DD);
        #pragma unroll
        for (int c = 0; c < 8; ++c)
            a[c] = __ldg((const float4*)&x0[row + c * 64 + u * 4]);
        if (u < 8) {
            float4 v = __ldg((const float4*)&x1[(long long)ec * (S1 * DD) + u * 4]);
            *(float4*)&sX1[el * X1PAD + u * 4] = v;
        }
        __syncwarp();

        // ---- W phase (packed f32x2 accumulation) ----
        {   // rank-4 job (p = u>>2, i = u&3)
            const float4 bq = *(const float4*)&myX1[s1a * 4];
            const float4 cq = *(const float4*)&myX1[s1b * 4];
            const float bv[4] = {bq.x, bq.y, bq.z, bq.w};
            const float cv[4] = {cq.x, cq.y, cq.z, cq.w};
            u64 w01 = 0ull, w23 = 0ull;
            #pragma unroll
            for (int j = 0; j < 4; ++j) {
                #pragma unroll
                for (int k = 0; k < 4; ++k) {
                    const u64 bc = dup2(bv[j] * cv[k]);
                    const ulonglong2 cf = *(const ulonglong2*)&sC4T[(j * 4 + k) * 64 + u * 4];
                    w01 = fma2(bc, cf.x, w01);
                    w23 = fma2(bc, cf.y, w23);
                }
            }
            *(ulonglong2*)&myW[128 + u * 4] = make_ulonglong2(w01, w23);
        }
        {   // rank-3 job h=0 (job = u)
            const float4 bq = *(const float4*)&myX1[s1c0 * 4];
            const float bv[4] = {bq.x, bq.y, bq.z, bq.w};
            u64 w01 = 0ull, w23 = 0ull;
            #pragma unroll
            for (int j = 0; j < 4; ++j) {
                const u64 bj = dup2(bv[j]);
                const ulonglong2 cf = *(const ulonglong2*)&sC3T[j * 128 + u * 4];
                w01 = fma2(bj, cf.x, w01);
                w23 = fma2(bj, cf.y, w23);
            }
            *(ulonglong2*)&myW[u * 4] = make_ulonglong2(w01, w23);
        }
        {   // rank-3 job h=1 (job = u+16)
            const float4 bq = *(const float4*)&myX1[s1c1 * 4];
            const float bv[4] = {bq.x, bq.y, bq.z, bq.w};
            u64 w01 = 0ull, w23 = 0ull;
            #pragma unroll
            for (int j = 0; j < 4; ++j) {
                const u64 bj = dup2(bv[j]);
                const ulonglong2 cf = *(const ulonglong2*)&sC3T[j * 128 + (u + 16) * 4];
                w01 = fma2(bj, cf.x, w01);
                w23 = fma2(bj, cf.y, w23);
            }
            *(ulonglong2*)&myW[(u + 16) * 4] = make_ulonglong2(w01, w23);
        }
        __syncwarp();

        // ---- contraction (packed f32x2): 12 sorted entries, flush at group end ----
        const long long obase = (long long)e * (SOUT * MUL * DD);
        u64 acc01 = 0ull, acc23 = 0ull;
        #pragma unroll
        for (int t = 0; t < 12; ++t) {
            const int w16  = (meta[t >> 1] >> ((t & 1) * 16)) & 0xffff;
            const int s0v  = w16 & 7;
            const int slot = (w16 >> 4) & 15;
            const float4 av = sel8(a, s0v);
            const ulonglong2 W0 = *(const ulonglong2*)&myW[slot * 16];
            const ulonglong2 W1 = *(const ulonglong2*)&myW[slot * 16 + 4];
            const ulonglong2 W2 = *(const ulonglong2*)&myW[slot * 16 + 8];
            const ulonglong2 W3 = *(const ulonglong2*)&myW[slot * 16 + 12];
            const u64 ax = dup2(av.x), ay = dup2(av.y), az = dup2(av.z), aw = dup2(av.w);
            acc01 = fma2(ax, W0.x, acc01); acc23 = fma2(ax, W0.y, acc23);
            acc01 = fma2(ay, W1.x, acc01); acc23 = fma2(ay, W1.y, acc23);
            acc01 = fma2(az, W2.x, acc01); acc23 = fma2(az, W2.y, acc23);
            acc01 = fma2(aw, W3.x, acc01); acc23 = fma2(aw, W3.y, acc23);
            if (w16 & (1 << 12)) {
                const int so = (w16 >> 8) & 7;
                if (valid) {
                    const float2 lo = unpack2(acc01);
                    const float2 hi = unpack2(acc23);
                    __stwt((float4*)&out[obase + so * 64 + u * 4],
                           make_float4(lo.x, lo.y, hi.x, hi.y));
                }
                acc01 = 0ull; acc23 = 0ull;
            }
        }
        if (valid && zmask) {
            const float4 z = make_float4(0.f, 0.f, 0.f, 0.f);
            #pragma unroll
            for (int so = 0; so < SOUT; ++so)
                if ((zmask >> so) & 1)
                    __stwt((float4*)&out[obase + so * 64 + u * 4], z);
        }
        __syncwarp();
    }
}

extern "C" void kernel_launch(void* const* d_in, const int* in_sizes, int n_in,
                              void* d_out, int out_size) {
    const float* x0 = (const float*)d_in[0];
    const int*   i0 = (const int*)d_in[1];
    const float* x1 = (const float*)d_in[2];
    const float* C3 = (const float*)d_in[3];
    const float* C4 = (const float*)d_in[4];
    const int*   p3 = (const int*)d_in[5];
    const int*   p4 = (const int*)d_in[6];
    float* out = (float*)d_out;
    const int E = in_sizes[1];

    prep_kernel<<<1, 32>>>(p3, p4);
    const int ngroups = (E + EPB - 1) / EPB;
    const int blocks = ngroups < GRID_BLOCKS ? ngroups : GRID_BLOCKS;
    if (E % EPB == 0)
        tp_kernel<true><<<blocks, THREADS>>>(x0, i0, x1, C3, C4, out, E);
    else
        tp_kernel<false><<<blocks, THREADS>>>(x0, i0, x1, C3, C4, out, E);
}